// round 10
// baseline (speedup 1.0000x reference)
#include <cuda_runtime.h>
#include <math.h>
#include <stdint.h>

#define Bsz   128
#define Tlen  256
#define NCLS  128
#define WD    512
#define UNITS 512
#define N4    2048      // 4*UNITS
#define KX    640       // NC + WD
#define KTOT  1152      // KX + UNITS
#define NCH   18        // KTOT / 64
#define NBLK  128       // persistent grid (1 block/SM, all co-resident)

typedef unsigned long long ull;

// ---------------- device scratch ----------------
__device__ float g_h [2][UNITS * Bsz];          // [u][b], double-buffered
__device__ float g_hT[Bsz * UNITS];             // [b][u], phase-2 staging
__device__ float g_c [UNITS * Bsz];             // [u][b]
__device__ int   g_prev[Bsz];                   // prev argmax (-1 => t==0)
__device__ ull   g_Wp[(size_t)128 * KTOT * 16]; // packed (w,w): [block][k][c]
__device__ float g_Wfb[(size_t)NCLS * N4];      // feedback rows, packed col order
__device__ float g_biasP[N4];                   // bias, packed col order
__device__ float g_SP[N4];                      // start-vec colsum, packed order
__device__ float g_xT[(size_t)Tlen * KX * Bsz]; // x transposed: [t][k][b]
__device__ volatile int g_arrive[NBLK];         // slot barrier arrivals
__device__ volatile int g_release;              // slot barrier release
__device__ unsigned g_pcnt;                     // phase-2 completion counter

__device__ __forceinline__ void ffma2(ull& d, ull a, ull b) {
    asm("fma.rn.f32x2 %0, %1, %2, %0;" : "+l"(d) : "l"(a), "l"(b));
}
__device__ __forceinline__ void cpa16(uint32_t dst, const void* src) {
    asm volatile("cp.async.cg.shared.global [%0], [%1], 16;" :: "r"(dst), "l"(src) : "memory");
}
__device__ __forceinline__ void cpa_commit() {
    asm volatile("cp.async.commit_group;" ::: "memory");
}

__device__ __forceinline__ void col2bc(int col, int& blk, int& c) {
    int g = col >> 9;
    int u = col & 511;
    blk   = u >> 2;
    c     = (u & 3) * 4 + g;
}

// slot-based grid barrier: no serialized atomics. Arrival value = t+1.
__device__ __forceinline__ void grid_sync(int t) {
    __syncthreads();
    if (threadIdx.x == 0) {
        __threadfence();                       // release: flush block's stores (+CCTL)
        g_arrive[blockIdx.x] = t + 1;
    }
    if (blockIdx.x == 0) {
        if (threadIdx.x < NBLK)
            while (g_arrive[threadIdx.x] < t + 1) __nanosleep(8);
        __syncthreads();
        if (threadIdx.x == 0) {
            __threadfence();
            g_release = t + 1;
        }
    }
    if (threadIdx.x == 0) {
        while (g_release < t + 1) __nanosleep(8);
        __threadfence();                       // acquire: invalidate L1 for fresh reads
    }
    __syncthreads();
}

// ---------------- launch 1: init state + pack bias/start-vec/feedback rows -------
__global__ void k_prep(const float* __restrict__ W, const float* __restrict__ bias) {
    int idx = blockIdx.x * blockDim.x + threadIdx.x;   // 262144 threads
    // pack misc (covers all 128*2048 indices)
    {
        int pi  = idx >> 11;
        int col = idx & 2047;
        int blk, c; col2bc(col, blk, c);
        int dst = blk * 16 + c;
        g_Wfb[(size_t)pi * N4 + dst] = W[(size_t)(KX + pi) * N4 + col];
        if (pi == 0) {
            g_biasP[dst] = bias[col];
            float s = 0.0f;
            #pragma unroll
            for (int i = 0; i < NCLS; i++) s += W[(size_t)(KX + i) * N4 + col];
            g_SP[dst] = s;
        }
    }
    if (idx < UNITS * Bsz) { g_h[0][idx] = 0.0f; g_c[idx] = 0.0f; }
    if (idx < Bsz)  g_prev[idx] = -1;
    if (idx < NBLK) g_arrive[idx] = 0;
    if (idx == 0) { g_release = 0; g_pcnt = 0; }
}

// ---------------- launch 2: pack weights ----------------
__global__ void k_packW(const float* __restrict__ W, const float* __restrict__ U) {
    int idx = blockIdx.x * blockDim.x + threadIdx.x;
    int k   = idx >> 11;
    int col = idx & 2047;
    if (k >= KTOT) return;
    float w = (k < KX) ? W[(size_t)k * N4 + col] : U[(size_t)(k - KX) * N4 + col];
    int blk, c; col2bc(col, blk, c);
    ull p;
    asm("mov.b64 %0, {%1, %2};" : "=l"(p) : "f"(w), "f"(w));
    g_Wp[((size_t)blk * KTOT + k) * 16 + c] = p;
}

// ---------------- launch 3: transpose x -> g_xT[t][k][b] ----------------
__global__ void k_xT(const float* __restrict__ xc, const float* __restrict__ xw) {
    __shared__ float tile[32][33];
    int t  = blockIdx.x;
    int kt = blockIdx.y;
    int bt = blockIdx.z;
    int tx = threadIdx.x;
    int ty = threadIdx.y;
    #pragma unroll
    for (int i = 0; i < 4; i++) {
        int b = bt * 32 + ty + 8 * i;
        int k = kt * 32 + tx;
        float v = (k < NCLS) ? xc[((size_t)b * Tlen + t) * NCLS + k]
                             : xw[((size_t)b * Tlen + t) * WD + (k - NCLS)];
        tile[ty + 8 * i][tx] = v;
    }
    __syncthreads();
    #pragma unroll
    for (int i = 0; i < 4; i++) {
        int k = kt * 32 + ty + 8 * i;
        int b = bt * 32 + tx;
        g_xT[((size_t)t * KX + k) * Bsz + b] = tile[tx][ty + 8 * i];
    }
}

// ---------------- launch 4 (global #6 -> ncu captures): persistent scan ----------
// dynamic smem: [ ws_all: KTOT*16 ull = 147456 B ][ vs: 2*64*132 f32 = 67584 B ]
#define WSALL_B (KTOT * 16 * 8)
#define VS_ELE  (64 * 132)
#define DSMEM   (WSALL_B + 2 * VS_ELE * 4)     // 215040 B

__global__ __launch_bounds__(256) void k_scan(const float* __restrict__ Ws,
                                              const float* __restrict__ bsv,
                                              float* __restrict__ out) {
    extern __shared__ char sm[];
    ull*   ws_all = (ull*)sm;                  // [KTOT][16]
    float* vsb    = (float*)(sm + WSALL_B);    // [2][64][132]
    __shared__ float p2h[UNITS];               // phase-2 h staging (one batch)
    __shared__ float p2red[NCLS];              // split-K partials
    __shared__ float cV[4];
    __shared__ int   cI[4];

    const int tid = threadIdx.x;
    const int bq  = tid & 63;
    const int cq  = tid >> 6;                  // local unit 0..3 (owns 4 gates)
    const int blk = blockIdx.x;
    const uint32_t vs_s = (uint32_t)__cvta_generic_to_shared(vsb);
    const uint32_t ws_s = (uint32_t)__cvta_generic_to_shared(ws_all);

    // preload this block's full weight slice into smem (once)
    {
        const char* src = (const char*)(g_Wp + (size_t)blk * KTOT * 16);
        #pragma unroll
        for (int i = 0; i < 36; i++) {         // 9216 x 16B / 256 thr
            int q = tid + 256 * i;
            cpa16(ws_s + q * 16, src + (size_t)q * 16);
        }
        cpa_commit();
        asm volatile("cp.async.wait_group 0;" ::: "memory");
        __syncthreads();
    }

    for (int t = 0; t < Tlen; t++) {
        const float* __restrict__ hin = g_h[t & 1];
        float* hout = g_h[(t + 1) & 1];

        // -------- phase 1 GEMM: z = x@W + h@U (K=1152), 16 cols x 128 b --------
        auto issue = [&](int ch, int buf) {
            const float* src = (ch < 10)
                ? g_xT + ((size_t)t * KX + ch * 64) * Bsz
                : hin  + (size_t)(ch - 10) * 64 * Bsz;
            uint32_t vdst = vs_s + buf * VS_ELE * 4;
            #pragma unroll
            for (int i = 0; i < 8; i++) {
                int vi = tid + 256 * i;                  // 0..2047 float4s
                int k  = vi >> 5;
                int b4 = vi & 31;
                cpa16(vdst + (k * 132 + b4 * 4) * 4, src + k * Bsz + b4 * 4);
            }
            cpa_commit();
        };

        ull acc[4] = {0ull, 0ull, 0ull, 0ull};
        issue(0, 0);
        issue(1, 1);

        for (int ch = 0; ch < NCH; ch++) {
            if (ch < NCH - 2) asm volatile("cp.async.wait_group 1;" ::: "memory");
            else              asm volatile("cp.async.wait_group 0;" ::: "memory");
            __syncthreads();

            const float* vrow = vsb + (ch & 1) * VS_ELE;
            const ull*   wrow = ws_all + ch * 64 * 16;

            #pragma unroll 8
            for (int k = 0; k < 64; k++) {
                ull hv = *(const ull*)(vrow + k * 132 + 2 * bq);
                const ull* wr = wrow + k * 16 + cq * 4;
                ulonglong2 wA = *(const ulonglong2*)&wr[0];
                ulonglong2 wB = *(const ulonglong2*)&wr[2];
                ffma2(acc[0], hv, wA.x);  ffma2(acc[1], hv, wA.y);
                ffma2(acc[2], hv, wB.x);  ffma2(acc[3], hv, wB.y);
            }
            __syncthreads();
            if (ch + 2 < NCH) issue(ch + 2, ch & 1);
        }

        // -------- wait for g_prev of step t-1 (phase 2 ran concurrently) --------
        if (t > 0) {
            if (tid == 0) {
                while (*(volatile unsigned*)&g_pcnt < (unsigned)(NBLK * t)) __nanosleep(8);
                __threadfence();               // invalidate L1 so g_prev reads are fresh
            }
            __syncthreads();
        }

        // -------- epilogue: gates (Keras i,f,g,o) -> new c, h --------
        const int u    = blk * 4 + cq;
        const int dstb = blk * 16 + cq * 4;
        float zl[4], zh[4];
        #pragma unroll
        for (int g = 0; g < 4; g++)
            asm("mov.b64 {%0, %1}, %2;" : "=f"(zl[g]), "=f"(zh[g]) : "l"(acc[g]));

        #pragma unroll
        for (int r = 0; r < 2; r++) {
            const int b  = 2 * bq + r;
            const int pi = *(volatile int*)&g_prev[b];
            float z[4];
            #pragma unroll
            for (int g = 0; g < 4; g++) {
                float add = (pi < 0) ? 1e-5f * g_SP[dstb + g]
                                     : __ldg(&g_Wfb[(size_t)pi * N4 + dstb + g]);
                z[g] = (r ? zh[g] : zl[g]) + g_biasP[dstb + g] + add;
            }
            float i_ = 1.0f / (1.0f + expf(-z[0]));
            float f_ = 1.0f / (1.0f + expf(-z[1]));
            float gv = tanhf(z[2]);
            float o_ = 1.0f / (1.0f + expf(-z[3]));
            float cn = f_ * g_c[(size_t)u * Bsz + b] + i_ * gv;
            float hn = o_ * tanhf(cn);
            g_c[(size_t)u * Bsz + b]    = cn;
            hout[(size_t)u * Bsz + b]   = hn;
            g_hT[(size_t)b * UNITS + u] = hn;
        }

        grid_sync(t);   // h(t+1)/g_hT complete + visible everywhere

        // -------- phase 2 (overlaps next step's GEMM): block blk -> batch blk ----
        {
            const int b = blk;
            p2h[tid]       = g_hT[(size_t)b * UNITS + tid];
            p2h[tid + 256] = g_hT[(size_t)b * UNITS + tid + 256];
            __syncthreads();

            const int j    = tid & 127;
            const int s    = tid >> 7;         // split-K half
            const int base = s * 256;
            float a = 0.0f;
            #pragma unroll 16
            for (int k = 0; k < 256; k++)
                a += p2h[base + k] * __ldg(&Ws[(size_t)(base + k) * NCLS + j]);
            if (s) p2red[j] = a;
            __syncthreads();

            if (!s) {
                float v  = a + p2red[j] + __ldg(&bsv[j]);
                int   bi = j;
                #pragma unroll
                for (int off = 16; off > 0; off >>= 1) {
                    float ov = __shfl_down_sync(0xffffffffu, v, off);
                    int   oi = __shfl_down_sync(0xffffffffu, bi, off);
                    if (ov > v || (ov == v && oi < bi)) { v = ov; bi = oi; }
                }
                if ((j & 31) == 0) { cV[j >> 5] = v; cI[j >> 5] = bi; }
            }
            __syncthreads();
            if (tid == 0) {
                float v  = cV[0];
                int   bi = cI[0];
                #pragma unroll
                for (int w = 1; w < 4; w++)
                    if (cV[w] > v || (cV[w] == v && cI[w] < bi)) { v = cV[w]; bi = cI[w]; }
                out[(size_t)b * Tlen + t] = (float)bi;   // float32 output
                g_prev[b] = bi;
                __threadfence();
                atomicAdd(&g_pcnt, 1u);
            }
            __syncthreads();
        }
    }
}

// ---------------- launch ----------------
extern "C" void kernel_launch(void* const* d_in, const int* in_sizes, int n_in,
                              void* d_out, int out_size) {
    (void)out_size;
    const float *xc = 0, *xw = 0, *W = 0, *U = 0, *bias = 0, *Ws = 0, *bs = 0;
    for (int i = 0; i < n_in; i++) {
        switch (in_sizes[i]) {
            case 4194304:  xc   = (const float*)d_in[i]; break;
            case 16777216: xw   = (const float*)d_in[i]; break;
            case 1572864:  W    = (const float*)d_in[i]; break;
            case 1048576:  U    = (const float*)d_in[i]; break;
            case 2048:     bias = (const float*)d_in[i]; break;
            case 65536:    Ws   = (const float*)d_in[i]; break;
            case 128:      bs   = (const float*)d_in[i]; break;
            default: break;
        }
    }
    if ((!xc || !xw || !W || !U || !bias || !Ws || !bs) && n_in >= 7) {
        xc = (const float*)d_in[0]; xw = (const float*)d_in[1];
        W  = (const float*)d_in[2]; U  = (const float*)d_in[3];
        bias = (const float*)d_in[4]; Ws = (const float*)d_in[5];
        bs = (const float*)d_in[6];
    }
    float* out = (float*)d_out;

    cudaFuncSetAttribute(k_scan, cudaFuncAttributeMaxDynamicSharedMemorySize, DSMEM);

    k_prep<<<(128 * 2048) / 256, 256>>>(W, bias);             // my launch 1
    k_packW<<<(KTOT * 2048) / 256, 256>>>(W, U);              // my launch 2
    {
        dim3 g(Tlen, KX / 32, Bsz / 32);
        dim3 b(32, 8);
        k_xT<<<g, b>>>(xc, xw);                               // my launch 3
    }
    k_scan<<<NBLK, 256, DSMEM>>>(Ws, bs, out);                // my launch 4 = global #6
}

// round 12
// speedup vs baseline: 1.2737x; 1.2737x over previous
#include <cuda_runtime.h>
#include <math.h>
#include <stdint.h>

#define Bsz   128
#define Tlen  256
#define NCLS  128
#define WD    512
#define UNITS 512
#define N4    2048      // 4*UNITS
#define KX    640       // NC + WD
#define KTOT  1152      // KX + UNITS
#define NCH   18        // KTOT / 64
#define NBLK  128       // persistent grid (1 block/SM, all co-resident)
#define NTHR  320       // 256 GEMM + 64 phase-2

typedef unsigned long long ull;

// ---------------- device scratch ----------------
__device__ float g_h [2][UNITS * Bsz];          // [u][b], double-buffered
__device__ float g_hT[Bsz * UNITS];             // [b][u], phase-2 staging
__device__ float g_c [UNITS * Bsz];             // [u][b]
__device__ int   g_prev[Bsz];                   // prev argmax (-1 => t==0)
__device__ ull   g_Wp[(size_t)128 * KTOT * 16]; // packed (w,w): [block][k][c]
__device__ float g_Wfb[(size_t)NCLS * N4];      // feedback rows, packed col order
__device__ float g_biasP[N4];                   // bias, packed col order
__device__ float g_SP[N4];                      // start-vec colsum, packed order
__device__ float g_xT[(size_t)Tlen * KX * Bsz]; // x transposed: [t][k][b]
__device__ volatile int g_arrive[NBLK];         // barrier arrival slots
__device__ volatile int g_release;              // barrier release flag
__device__ unsigned g_pcnt;                     // phase-2 completion counter

__device__ __forceinline__ void ffma2(ull& d, ull a, ull b) {
    asm("fma.rn.f32x2 %0, %1, %2, %0;" : "+l"(d) : "l"(a), "l"(b));
}
__device__ __forceinline__ void cpa16(uint32_t dst, const void* src) {
    asm volatile("cp.async.cg.shared.global [%0], [%1], 16;" :: "r"(dst), "l"(src) : "memory");
}
__device__ __forceinline__ void cpa_commit() {
    asm volatile("cp.async.commit_group;" ::: "memory");
}
#define BAR_G() asm volatile("bar.sync 1, 256;" ::: "memory")   // GEMM warps
#define BAR_P() asm volatile("bar.sync 2, 64;"  ::: "memory")   // phase-2 warps

__device__ __forceinline__ void col2bc(int col, int& blk, int& c) {
    int g = col >> 9;
    int u = col & 511;
    blk   = u >> 2;
    c     = (u & 3) * 4 + g;
}

// ---------------- launch 1: init state + pack bias/start-vec/feedback rows -------
__global__ void k_prep(const float* __restrict__ W, const float* __restrict__ bias) {
    int idx = blockIdx.x * blockDim.x + threadIdx.x;   // 262144 threads
    {
        int pi  = idx >> 11;
        int col = idx & 2047;
        int blk, c; col2bc(col, blk, c);
        int dst = blk * 16 + c;
        g_Wfb[(size_t)pi * N4 + dst] = W[(size_t)(KX + pi) * N4 + col];
        if (pi == 0) {
            g_biasP[dst] = bias[col];
            float s = 0.0f;
            #pragma unroll
            for (int i = 0; i < NCLS; i++) s += W[(size_t)(KX + i) * N4 + col];
            g_SP[dst] = s;
        }
    }
    if (idx < UNITS * Bsz) { g_h[0][idx] = 0.0f; g_c[idx] = 0.0f; }
    if (idx < Bsz)  g_prev[idx] = -1;
    if (idx < NBLK) g_arrive[idx] = 0;
    if (idx == 0) { g_release = 0; g_pcnt = 0; }
}

// ---------------- launch 2: pack weights ----------------
__global__ void k_packW(const float* __restrict__ W, const float* __restrict__ U) {
    int idx = blockIdx.x * blockDim.x + threadIdx.x;
    int k   = idx >> 11;
    int col = idx & 2047;
    if (k >= KTOT) return;
    float w = (k < KX) ? W[(size_t)k * N4 + col] : U[(size_t)(k - KX) * N4 + col];
    int blk, c; col2bc(col, blk, c);
    ull p;
    asm("mov.b64 %0, {%1, %2};" : "=l"(p) : "f"(w), "f"(w));
    g_Wp[((size_t)blk * KTOT + k) * 16 + c] = p;
}

// ---------------- launch 3: transpose x -> g_xT[t][k][b] ----------------
__global__ void k_xT(const float* __restrict__ xc, const float* __restrict__ xw) {
    __shared__ float tile[32][33];
    int t  = blockIdx.x;
    int kt = blockIdx.y;
    int bt = blockIdx.z;
    int tx = threadIdx.x;
    int ty = threadIdx.y;
    #pragma unroll
    for (int i = 0; i < 4; i++) {
        int b = bt * 32 + ty + 8 * i;
        int k = kt * 32 + tx;
        float v = (k < NCLS) ? xc[((size_t)b * Tlen + t) * NCLS + k]
                             : xw[((size_t)b * Tlen + t) * WD + (k - NCLS)];
        tile[ty + 8 * i][tx] = v;
    }
    __syncthreads();
    #pragma unroll
    for (int i = 0; i < 4; i++) {
        int k = kt * 32 + ty + 8 * i;
        int b = bt * 32 + tx;
        g_xT[((size_t)t * KX + k) * Bsz + b] = tile[tx][ty + 8 * i];
    }
}

// ---------------- launch 4 (global #6 -> ncu): persistent warp-specialized scan --
// dynamic smem: [ ws_all: KTOT*16 ull = 147456 B ][ vs: 2*64*132 f32 = 67584 B ]
#define WSALL_B (KTOT * 16 * 8)
#define VS_ELE  (64 * 132)
#define DSMEM   (WSALL_B + 2 * VS_ELE * 4)     // 215040 B

__global__ __launch_bounds__(NTHR, 1) void k_scan(const float* __restrict__ Ws,
                                                  const float* __restrict__ bsv,
                                                  float* __restrict__ out) {
    extern __shared__ char sm[];
    ull*   ws_all = (ull*)sm;                  // [KTOT][16]
    float* vsb    = (float*)(sm + WSALL_B);    // [2][64][132]
    __shared__ float p2h[UNITS];               // phase-2 h staging
    __shared__ float cV2[2];
    __shared__ int   cI2[2];

    const int tid = threadIdx.x;
    const int blk = blockIdx.x;

    if (tid < 256) {
        // ===================== GEMM role (warps 0-7) =====================
        const int bq = tid & 63;
        const int cq = tid >> 6;               // local unit 0..3 (owns 4 gates)
        const uint32_t vs_s = (uint32_t)__cvta_generic_to_shared(vsb);
        const uint32_t ws_s = (uint32_t)__cvta_generic_to_shared(ws_all);

        // preload this block's full weight slice into smem (once)
        {
            const char* src = (const char*)(g_Wp + (size_t)blk * KTOT * 16);
            #pragma unroll
            for (int i = 0; i < 36; i++) {     // 9216 x 16B / 256 thr
                int q = tid + 256 * i;
                cpa16(ws_s + q * 16, src + (size_t)q * 16);
            }
            cpa_commit();
            asm volatile("cp.async.wait_group 0;" ::: "memory");
            BAR_G();
        }

        auto issue = [&](int tt, int ch, int buf) {
            const float* src = (ch < 10)
                ? g_xT + ((size_t)tt * KX + ch * 64) * Bsz
                : g_h[tt & 1] + (size_t)(ch - 10) * 64 * Bsz;
            uint32_t vdst = vs_s + buf * VS_ELE * 4;
            #pragma unroll
            for (int i = 0; i < 8; i++) {
                int vi = tid + 256 * i;        // 0..2047 float4s
                int k  = vi >> 5;
                int b4 = vi & 31;
                cpa16(vdst + (k * 132 + b4 * 4) * 4, src + k * Bsz + b4 * 4);
            }
            cpa_commit();
        };

        issue(0, 0, 0);
        issue(0, 1, 1);

        for (int t = 0; t < Tlen; t++) {
            ull acc[4] = {0ull, 0ull, 0ull, 0ull};

            for (int ch = 0; ch < NCH; ch++) {
                if (ch < NCH - 2) asm volatile("cp.async.wait_group 1;" ::: "memory");
                else              asm volatile("cp.async.wait_group 0;" ::: "memory");
                BAR_G();

                const float* vrow = vsb + (ch & 1) * VS_ELE;
                const ull*   wrow = ws_all + ch * 64 * 16;

                #pragma unroll 8
                for (int k = 0; k < 64; k++) {
                    ull hv = *(const ull*)(vrow + k * 132 + 2 * bq);
                    const ull* wr = wrow + k * 16 + cq * 4;
                    ulonglong2 wA = *(const ulonglong2*)&wr[0];
                    ulonglong2 wB = *(const ulonglong2*)&wr[2];
                    ffma2(acc[0], hv, wA.x);  ffma2(acc[1], hv, wA.y);
                    ffma2(acc[2], hv, wB.x);  ffma2(acc[3], hv, wB.y);
                }
                BAR_G();

                if (ch + 2 < NCH) {
                    if (ch + 2 == 10 && t > 0) {
                        // first h-dependent chunk: need epilogue(t-1) of ALL blocks
                        if (tid == 0) {
                            while (g_release < t) __nanosleep(8);
                            __threadfence();   // acquire (IVALL)
                        }
                        BAR_G();
                    }
                    issue(t, ch + 2, ch & 1);
                }
            }

            // prefetch next step's x chunks (no dependencies)
            if (t + 1 < Tlen) {
                issue(t + 1, 0, 0);
                issue(t + 1, 1, 1);
            }

            // wait for phase-2 of step t-1 (g_prev) — normally already done
            if (t > 0) {
                if (tid == 0) {
                    while (*(volatile unsigned*)&g_pcnt < (unsigned)(NBLK * t)) __nanosleep(8);
                    __threadfence();
                }
                BAR_G();
            }

            // epilogue: gates (Keras i,f,g,o) -> new c, h
            float* hout = g_h[(t + 1) & 1];
            const int u    = blk * 4 + cq;
            const int dstb = blk * 16 + cq * 4;
            float zl[4], zh[4];
            #pragma unroll
            for (int g = 0; g < 4; g++)
                asm("mov.b64 {%0, %1}, %2;" : "=f"(zl[g]), "=f"(zh[g]) : "l"(acc[g]));

            #pragma unroll
            for (int r = 0; r < 2; r++) {
                const int b  = 2 * bq + r;
                const int pi = *(volatile int*)&g_prev[b];
                float z[4];
                #pragma unroll
                for (int g = 0; g < 4; g++) {
                    float add = (pi < 0) ? 1e-5f * g_SP[dstb + g]
                                         : __ldg(&g_Wfb[(size_t)pi * N4 + dstb + g]);
                    z[g] = (r ? zh[g] : zl[g]) + g_biasP[dstb + g] + add;
                }
                float i_ = 1.0f / (1.0f + expf(-z[0]));
                float f_ = 1.0f / (1.0f + expf(-z[1]));
                float gv = tanhf(z[2]);
                float o_ = 1.0f / (1.0f + expf(-z[3]));
                float cn = f_ * g_c[(size_t)u * Bsz + b] + i_ * gv;
                float hn = o_ * tanhf(cn);
                g_c[(size_t)u * Bsz + b]    = cn;
                hout[(size_t)u * Bsz + b]   = hn;
                g_hT[(size_t)b * UNITS + u] = hn;
            }

            BAR_G();                           // all epilogue stores executed
            if (tid == 0) {
                __threadfence();               // release
                g_arrive[blk] = t + 1;
            }
        }
    } else {
        // ===================== phase-2 role (warps 8-9) =====================
        const int t2 = tid - 256;              // 0..63
        const int j1 = t2;
        const int j2 = t2 + 64;
        const float b1 = __ldg(&bsv[j1]);
        const float b2 = __ldg(&bsv[j2]);

        for (int t = 0; t < Tlen; t++) {
            if (blk == 0) {
                // release duty: poll all arrival slots, then publish release
                while (g_arrive[t2] < t + 1)      __nanosleep(16);
                while (g_arrive[t2 + 64] < t + 1) __nanosleep(16);
                BAR_P();
                if (t2 == 0) {
                    __threadfence();
                    g_release = t + 1;
                }
            }
            if (t2 == 0) {
                while (g_release < t + 1) __nanosleep(16);
                __threadfence();               // acquire (IVALL)
            }
            BAR_P();

            // stage h(t+1) for batch = blk
            #pragma unroll
            for (int q = 0; q < 2; q++) {
                int idx = t2 + 64 * q;         // 0..127 float4s
                *(float4*)&p2h[idx * 4] =
                    *(const float4*)&g_hT[(size_t)blk * UNITS + idx * 4];
            }
            BAR_P();

            // logits j1, j2 over K=512
            float v1 = b1, v2 = b2;
            #pragma unroll 8
            for (int k = 0; k < UNITS; k++) {
                float hk = p2h[k];
                v1 += hk * __ldg(&Ws[(size_t)k * NCLS + j1]);
                v2 += hk * __ldg(&Ws[(size_t)k * NCLS + j2]);
            }
            // per-thread best (tie -> lower index; j1 < j2)
            float v  = (v2 > v1) ? v2 : v1;
            int   bi = (v2 > v1) ? j2 : j1;
            // warp reduce
            #pragma unroll
            for (int off = 16; off > 0; off >>= 1) {
                float ov = __shfl_down_sync(0xffffffffu, v, off);
                int   oi = __shfl_down_sync(0xffffffffu, bi, off);
                if (ov > v || (ov == v && oi < bi)) { v = ov; bi = oi; }
            }
            if ((t2 & 31) == 0) { cV2[t2 >> 5] = v; cI2[t2 >> 5] = bi; }
            BAR_P();
            if (t2 == 0) {
                float vv = cV2[0]; int ii = cI2[0];
                if (cV2[1] > vv || (cV2[1] == vv && cI2[1] < ii)) { vv = cV2[1]; ii = cI2[1]; }
                out[(size_t)blk * Tlen + t] = (float)ii;   // float32 output
                g_prev[blk] = ii;
                __threadfence();
                atomicAdd(&g_pcnt, 1u);
            }
            BAR_P();
        }
    }
}

// ---------------- launch ----------------
extern "C" void kernel_launch(void* const* d_in, const int* in_sizes, int n_in,
                              void* d_out, int out_size) {
    (void)out_size;
    const float *xc = 0, *xw = 0, *W = 0, *U = 0, *bias = 0, *Ws = 0, *bs = 0;
    for (int i = 0; i < n_in; i++) {
        switch (in_sizes[i]) {
            case 4194304:  xc   = (const float*)d_in[i]; break;
            case 16777216: xw   = (const float*)d_in[i]; break;
            case 1572864:  W    = (const float*)d_in[i]; break;
            case 1048576:  U    = (const float*)d_in[i]; break;
            case 2048:     bias = (const float*)d_in[i]; break;
            case 65536:    Ws   = (const float*)d_in[i]; break;
            case 128:      bs   = (const float*)d_in[i]; break;
            default: break;
        }
    }
    if ((!xc || !xw || !W || !U || !bias || !Ws || !bs) && n_in >= 7) {
        xc = (const float*)d_in[0]; xw = (const float*)d_in[1];
        W  = (const float*)d_in[2]; U  = (const float*)d_in[3];
        bias = (const float*)d_in[4]; Ws = (const float*)d_in[5];
        bs = (const float*)d_in[6];
    }
    float* out = (float*)d_out;

    cudaFuncSetAttribute(k_scan, cudaFuncAttributeMaxDynamicSharedMemorySize, DSMEM);

    k_prep<<<(128 * 2048) / 256, 256>>>(W, bias);             // my launch 1
    k_packW<<<(KTOT * 2048) / 256, 256>>>(W, U);              // my launch 2
    {
        dim3 g(Tlen, KX / 32, Bsz / 32);
        dim3 b(32, 8);
        k_xT<<<g, b>>>(xc, xw);                               // my launch 3
    }
    k_scan<<<NBLK, NTHR, DSMEM>>>(Ws, bs, out);               // my launch 4 = global #6
}

// round 16
// speedup vs baseline: 1.4108x; 1.1076x over previous
#include <cuda_runtime.h>
#include <math.h>
#include <stdint.h>

#define Bsz   128
#define Tlen  256
#define NCLS  128
#define WD    512
#define UNITS 512
#define N4    2048      // 4*UNITS
#define KX    640       // NC + WD
#define KTOT  1152      // KX + UNITS
#define NCH   18        // KTOT / 64
#define NBLK  128       // persistent grid (1 block/SM, all co-resident)
#define NTHR  320       // 256 GEMM + 64 phase-2

typedef unsigned long long ull;

// ---------------- device scratch ----------------
__device__ float g_h [2][UNITS * Bsz];          // [u][b], double-buffered
__device__ float g_hT[Bsz * UNITS];             // [b][u], phase-2 staging
__device__ float g_c [UNITS * Bsz];             // [u][b]
__device__ int   g_prev[Bsz];                   // prev argmax (-1 => t==0)
__device__ float g_Wf[(size_t)128 * KTOT * 16]; // packed plain floats: [block][k][c]
__device__ float g_Wfb[(size_t)NCLS * N4];      // feedback rows, packed col order
__device__ float g_biasP[N4];                   // bias, packed col order
__device__ float g_SP[N4];                      // start-vec colsum, packed order
__device__ float g_xT[(size_t)Tlen * KX * Bsz]; // x transposed: [t][k][b]
__device__ volatile int g_arrive[NBLK];         // barrier arrival slots
__device__ volatile int g_release;              // barrier release flag
__device__ unsigned g_pcnt;                     // phase-2 completion counter

__device__ __forceinline__ void ffma2(ull& d, ull a, ull b) {
    asm("fma.rn.f32x2 %0, %1, %2, %0;" : "+l"(d) : "l"(a), "l"(b));
}
__device__ __forceinline__ void cpa16(uint32_t dst, const void* src) {
    asm volatile("cp.async.cg.shared.global [%0], [%1], 16;" :: "r"(dst), "l"(src) : "memory");
}
__device__ __forceinline__ void cpa_commit() {
    asm volatile("cp.async.commit_group;" ::: "memory");
}
#define BAR_G() asm volatile("bar.sync 1, 256;" ::: "memory")   // GEMM warps
#define BAR_P() asm volatile("bar.sync 2, 64;"  ::: "memory")   // phase-2 warps

__device__ __forceinline__ void col2bc(int col, int& blk, int& c) {
    int g = col >> 9;
    int u = col & 511;
    blk   = u >> 2;
    c     = (u & 3) * 4 + g;
}

// ---------------- launch 1: init state + pack bias/start-vec/feedback rows -------
__global__ void k_prep(const float* __restrict__ W, const float* __restrict__ bias) {
    int idx = blockIdx.x * blockDim.x + threadIdx.x;   // 262144 threads
    {
        int pi  = idx >> 11;
        int col = idx & 2047;
        int blk, c; col2bc(col, blk, c);
        int dst = blk * 16 + c;
        g_Wfb[(size_t)pi * N4 + dst] = W[(size_t)(KX + pi) * N4 + col];
        if (pi == 0) {
            g_biasP[dst] = bias[col];
            float s = 0.0f;
            #pragma unroll
            for (int i = 0; i < NCLS; i++) s += W[(size_t)(KX + i) * N4 + col];
            g_SP[dst] = s;
        }
    }
    if (idx < UNITS * Bsz) { g_h[0][idx] = 0.0f; g_c[idx] = 0.0f; }
    if (idx < Bsz)  g_prev[idx] = -1;
    if (idx < NBLK) g_arrive[idx] = 0;
    if (idx == 0) { g_release = 0; g_pcnt = 0; }
}

// ---------------- launch 2: pack weights (plain floats, packed col order) --------
__global__ void k_packW(const float* __restrict__ W, const float* __restrict__ U) {
    int idx = blockIdx.x * blockDim.x + threadIdx.x;
    int k   = idx >> 11;
    int col = idx & 2047;
    if (k >= KTOT) return;
    float w = (k < KX) ? W[(size_t)k * N4 + col] : U[(size_t)(k - KX) * N4 + col];
    int blk, c; col2bc(col, blk, c);
    g_Wf[((size_t)blk * KTOT + k) * 16 + c] = w;
}

// ---------------- launch 3: transpose x -> g_xT[t][k][b] ----------------
__global__ void k_xT(const float* __restrict__ xc, const float* __restrict__ xw) {
    __shared__ float tile[32][33];
    int t  = blockIdx.x;
    int kt = blockIdx.y;
    int bt = blockIdx.z;
    int tx = threadIdx.x;
    int ty = threadIdx.y;
    #pragma unroll
    for (int i = 0; i < 4; i++) {
        int b = bt * 32 + ty + 8 * i;
        int k = kt * 32 + tx;
        float v = (k < NCLS) ? xc[((size_t)b * Tlen + t) * NCLS + k]
                             : xw[((size_t)b * Tlen + t) * WD + (k - NCLS)];
        tile[ty + 8 * i][tx] = v;
    }
    __syncthreads();
    #pragma unroll
    for (int i = 0; i < 4; i++) {
        int k = kt * 32 + ty + 8 * i;
        int b = bt * 32 + tx;
        g_xT[((size_t)t * KX + k) * Bsz + b] = tile[tx][ty + 8 * i];
    }
}

// ---------------- launch 4 (global #6 -> ncu): persistent warp-specialized scan --
// dynamic smem: [ ws: KTOT*16 f32 = 73728 B ][ vs: 2*64*128 f32 = 65536 B ]
#define WSALL_B (KTOT * 16 * 4)
#define VS_ELE  (64 * 128)
#define DSMEM   (WSALL_B + 2 * VS_ELE * 4)     // 139264 B

__global__ __launch_bounds__(NTHR, 1) void k_scan(const float* __restrict__ Ws,
                                                  const float* __restrict__ bsv,
                                                  float* __restrict__ out) {
    extern __shared__ char sm[];
    float* ws_f = (float*)sm;                  // [KTOT][16]
    float* vsb  = (float*)(sm + WSALL_B);      // [2][64][128]
    __shared__ float p2h[UNITS];               // phase-2 h staging
    __shared__ float cV2[2];
    __shared__ int   cI2[2];

    const int tid = threadIdx.x;
    const int blk = blockIdx.x;

    if (tid < 256) {
        // ===================== GEMM role (warps 0-7) =====================
        // warp-internal layout: cq inner (broadcast-friendly)
        const int cq = tid & 3;                // local unit 0..3 (owns 4 gate-cols)
        const int bq = tid >> 2;               // batch pair 0..63
        const uint32_t vs_s = (uint32_t)__cvta_generic_to_shared(vsb);
        const uint32_t ws_s = (uint32_t)__cvta_generic_to_shared(ws_f);

        // preload this block's full weight slice into smem (once): 73728 B
        {
            const char* src = (const char*)(g_Wf + (size_t)blk * KTOT * 16);
            #pragma unroll
            for (int i = 0; i < 18; i++) {     // 4608 x 16B / 256 thr
                int q = tid + 256 * i;
                cpa16(ws_s + q * 16, src + (size_t)q * 16);
            }
            cpa_commit();
            asm volatile("cp.async.wait_group 0;" ::: "memory");
            BAR_G();
        }

        auto issue = [&](int tt, int ch, int buf) {
            const float* src = (ch < 10)
                ? g_xT + ((size_t)tt * KX + ch * 64) * Bsz
                : g_h[tt & 1] + (size_t)(ch - 10) * 64 * Bsz;
            uint32_t vdst = vs_s + buf * VS_ELE * 4;
            #pragma unroll
            for (int i = 0; i < 8; i++) {
                int vi = tid + 256 * i;        // 0..2047 float4s
                int k  = vi >> 5;
                int b4 = vi & 31;
                cpa16(vdst + (k * 128 + b4 * 4) * 4, src + k * Bsz + b4 * 4);
            }
            cpa_commit();
        };

        issue(0, 0, 0);
        issue(0, 1, 1);

        for (int t = 0; t < Tlen; t++) {
            ull a00 = 0ull, a01 = 0ull, a10 = 0ull, a11 = 0ull;
            // a00=(b0;c0,c1) a01=(b0;c2,c3) a10=(b1;c0,c1) a11=(b1;c2,c3)

            for (int ch = 0; ch < NCH; ch++) {
                if (ch < NCH - 2) asm volatile("cp.async.wait_group 1;" ::: "memory");
                else              asm volatile("cp.async.wait_group 0;" ::: "memory");
                BAR_G();

                const float* vrow = vsb + (ch & 1) * VS_ELE;
                const float* wrow = ws_f + ch * 64 * 16;

                #pragma unroll 8
                for (int k = 0; k < 64; k++) {
                    float2 hv = *(const float2*)(vrow + k * 128 + 2 * bq);
                    ulonglong2 ww = *(const ulonglong2*)(wrow + k * 16 + cq * 4);
                    ull vb0, vb1;
                    asm("mov.b64 %0, {%1, %1};" : "=l"(vb0) : "f"(hv.x));
                    asm("mov.b64 %0, {%1, %1};" : "=l"(vb1) : "f"(hv.y));
                    ffma2(a00, vb0, ww.x);  ffma2(a01, vb0, ww.y);
                    ffma2(a10, vb1, ww.x);  ffma2(a11, vb1, ww.y);
                }
                BAR_G();

                if (ch + 2 < NCH) {
                    if (ch + 2 == 10 && t > 0) {
                        // first h-dependent chunk: need epilogue(t-1) of ALL blocks
                        if (tid == 0) {
                            while (g_release < t) __nanosleep(8);
                            __threadfence();   // acquire
                        }
                        BAR_G();
                    }
                    issue(t, ch + 2, ch & 1);
                }
            }

            // prefetch next step's x chunks (no dependencies)
            if (t + 1 < Tlen) {
                issue(t + 1, 0, 0);
                issue(t + 1, 1, 1);
            }

            // wait for phase-2 of step t-1 (g_prev) — normally already done
            if (t > 0) {
                if (tid == 0) {
                    while (*(volatile unsigned*)&g_pcnt < (unsigned)(NBLK * t)) __nanosleep(8);
                    __threadfence();
                }
                BAR_G();
            }

            // epilogue: gates (Keras i,f,g,o) -> new c, h
            float* hout = g_h[(t + 1) & 1];
            const int u    = blk * 4 + cq;
            const int dstb = blk * 16 + cq * 4;
            float zz[2][4];
            asm("mov.b64 {%0, %1}, %2;" : "=f"(zz[0][0]), "=f"(zz[0][1]) : "l"(a00));
            asm("mov.b64 {%0, %1}, %2;" : "=f"(zz[0][2]), "=f"(zz[0][3]) : "l"(a01));
            asm("mov.b64 {%0, %1}, %2;" : "=f"(zz[1][0]), "=f"(zz[1][1]) : "l"(a10));
            asm("mov.b64 {%0, %1}, %2;" : "=f"(zz[1][2]), "=f"(zz[1][3]) : "l"(a11));

            #pragma unroll
            for (int r = 0; r < 2; r++) {
                const int b  = 2 * bq + r;
                const int pi = *(volatile int*)&g_prev[b];
                float z[4];
                #pragma unroll
                for (int g = 0; g < 4; g++) {
                    float add = (pi < 0) ? 1e-5f * g_SP[dstb + g]
                                         : __ldg(&g_Wfb[(size_t)pi * N4 + dstb + g]);
                    z[g] = zz[r][g] + g_biasP[dstb + g] + add;
                }
                float i_ = 1.0f / (1.0f + expf(-z[0]));
                float f_ = 1.0f / (1.0f + expf(-z[1]));
                float gv = tanhf(z[2]);
                float o_ = 1.0f / (1.0f + expf(-z[3]));
                float cn = f_ * g_c[(size_t)u * Bsz + b] + i_ * gv;
                float hn = o_ * tanhf(cn);
                g_c[(size_t)u * Bsz + b]    = cn;
                hout[(size_t)u * Bsz + b]   = hn;
                g_hT[(size_t)b * UNITS + u] = hn;
            }

            BAR_G();                           // all epilogue stores executed
            if (tid == 0) {
                __threadfence();               // release
                g_arrive[blk] = t + 1;
            }
        }
    } else {
        // ===================== phase-2 role (warps 8-9) =====================
        const int t2 = tid - 256;              // 0..63
        const int j1 = t2;
        const int j2 = t2 + 64;
        const float b1 = __ldg(&bsv[j1]);
        const float b2 = __ldg(&bsv[j2]);

        for (int t = 0; t < Tlen; t++) {
            if (blk == 0) {
                // release duty: poll all arrival slots, then publish release
                while (g_arrive[t2] < t + 1)      __nanosleep(16);
                while (g_arrive[t2 + 64] < t + 1) __nanosleep(16);
                BAR_P();
                if (t2 == 0) {
                    __threadfence();
                    g_release = t + 1;
                }
            }
            if (t2 == 0) {
                while (g_release < t + 1) __nanosleep(16);
                __threadfence();               // acquire
            }
            BAR_P();

            // stage h(t+1) for batch = blk
            #pragma unroll
            for (int q = 0; q < 2; q++) {
                int idx = t2 + 64 * q;         // 0..127 float4s
                *(float4*)&p2h[idx * 4] =
                    *(const float4*)&g_hT[(size_t)blk * UNITS + idx * 4];
            }
            BAR_P();

            // logits j1, j2 over K=512
            float v1 = b1, v2 = b2;
            #pragma unroll 8
            for (int k = 0; k < UNITS; k++) {
                float hk = p2h[k];
                v1 += hk * __ldg(&Ws[(size_t)k * NCLS + j1]);
                v2 += hk * __ldg(&Ws[(size_t)k * NCLS + j2]);
            }
            float v  = (v2 > v1) ? v2 : v1;
            int   bi = (v2 > v1) ? j2 : j1;
            #pragma unroll
            for (int off = 16; off > 0; off >>= 1) {
                float ov = __shfl_down_sync(0xffffffffu, v, off);
                int   oi = __shfl_down_sync(0xffffffffu, bi, off);
                if (ov > v || (ov == v && oi < bi)) { v = ov; bi = oi; }
            }
            if ((t2 & 31) == 0) { cV2[t2 >> 5] = v; cI2[t2 >> 5] = bi; }
            BAR_P();
            if (t2 == 0) {
                float vv = cV2[0]; int ii = cI2[0];
                if (cV2[1] > vv || (cV2[1] == vv && cI2[1] < ii)) { vv = cV2[1]; ii = cI2[1]; }
                out[(size_t)blk * Tlen + t] = (float)ii;   // float32 output
                g_prev[blk] = ii;
                __threadfence();
                atomicAdd(&g_pcnt, 1u);
            }
            BAR_P();
        }
    }
}

// ---------------- launch ----------------
extern "C" void kernel_launch(void* const* d_in, const int* in_sizes, int n_in,
                              void* d_out, int out_size) {
    (void)out_size;
    const float *xc = 0, *xw = 0, *W = 0, *U = 0, *bias = 0, *Ws = 0, *bs = 0;
    for (int i = 0; i < n_in; i++) {
        switch (in_sizes[i]) {
            case 4194304:  xc   = (const float*)d_in[i]; break;
            case 16777216: xw   = (const float*)d_in[i]; break;
            case 1572864:  W    = (const float*)d_in[i]; break;
            case 1048576:  U    = (const float*)d_in[i]; break;
            case 2048:     bias = (const float*)d_in[i]; break;
            case 65536:    Ws   = (const float*)d_in[i]; break;
            case 128:      bs   = (const float*)d_in[i]; break;
            default: break;
        }
    }
    if ((!xc || !xw || !W || !U || !bias || !Ws || !bs) && n_in >= 7) {
        xc = (const float*)d_in[0]; xw = (const float*)d_in[1];
        W  = (const float*)d_in[2]; U  = (const float*)d_in[3];
        bias = (const float*)d_in[4]; Ws = (const float*)d_in[5];
        bs = (const float*)d_in[6];
    }
    float* out = (float*)d_out;

    cudaFuncSetAttribute(k_scan, cudaFuncAttributeMaxDynamicSharedMemorySize, DSMEM);

    k_prep<<<(128 * 2048) / 256, 256>>>(W, bias);             // my launch 1
    k_packW<<<(KTOT * 2048) / 256, 256>>>(W, U);              // my launch 2
    {
        dim3 g(Tlen, KX / 32, Bsz / 32);
        dim3 b(32, 8);
        k_xT<<<g, b>>>(xc, xw);                               // my launch 3
    }
    k_scan<<<NBLK, NTHR, DSMEM>>>(Ws, bs, out);               // my launch 4 = global #6
}